// round 16
// baseline (speedup 1.0000x reference)
#include <cuda_runtime.h>
#include <cuda_bf16.h>
#include <cstdint>
#include <cstddef>

// Problem constants
#define S_LEN  2048
#define EMB    1024
#define NH     16
#define HD     64
#define BATCH  2
#define MROWS  (BATCH * S_LEN)   // 4096

// Scratch in device globals (no allocation allowed)
__device__ float g_q[(size_t)BATCH * NH * S_LEN * HD];     // head-dim permuted
__device__ float g_k[(size_t)BATCH * NH * S_LEN * HD];     // head-dim permuted
__device__ float g_v[(size_t)BATCH * NH * S_LEN * HD];     // natural
__device__ float g_ctx[(size_t)BATCH * S_LEN * EMB];       // e-dim permuted
__device__ float g_xt[(size_t)MROWS * EMB];                // tf32, e-dim permuted
__device__ float g_wt[4ULL * EMB * EMB];                   // transposed, tf32, k permuted

// ---------------------------------------------------------------------------
// Helpers
// ---------------------------------------------------------------------------
__device__ __forceinline__ uint32_t smem_u32(const void* p) {
    uint32_t a;
    asm("{ .reg .u64 t; cvta.to.shared.u64 t, %1; cvt.u32.u64 %0, t; }" : "=r"(a) : "l"(p));
    return a;
}
__device__ __forceinline__ float to_tf32(float x) {
    float y;
    asm("cvt.rna.tf32.f32 %0, %1;" : "=f"(y) : "f"(x));
    return y;
}
// permutation of the contraction axis within 8-blocks: logical j -> physical p
// p(j) = 2*(j&3) + (j>>2)  => pairs (j, j+4) become physically adjacent
__device__ __forceinline__ int perm8(int d) {
    return (d & ~7) | (2 * (d & 3) + ((d >> 2) & 1));
}

#define CP_ASYNC16(sa, gp) \
    asm volatile("cp.async.cg.shared.global [%0], [%1], 16;" :: "r"(sa), "l"(gp) : "memory")
#define CP_COMMIT() asm volatile("cp.async.commit_group;" ::: "memory")
#define CP_WAIT(n)  asm volatile("cp.async.wait_group %0;" :: "n"(n) : "memory")

// m16n8k8 tf32 mma: D += A * B  (A row-major m16k8 frag, B col-major n8k8 frag)
__device__ __forceinline__ void mma1688(float* c, const uint32_t* a, const uint32_t* b) {
    asm volatile(
        "mma.sync.aligned.m16n8k8.row.col.f32.tf32.tf32.f32 "
        "{%0,%1,%2,%3}, {%4,%5,%6,%7}, {%8,%9}, {%0,%1,%2,%3};"
        : "+f"(c[0]), "+f"(c[1]), "+f"(c[2]), "+f"(c[3])
        : "r"(a[0]), "r"(a[1]), "r"(a[2]), "r"(a[3]), "r"(b[0]), "r"(b[1]));
}

// ---------------------------------------------------------------------------
// x -> tf32-rounded copy with e-dim permutation
// ---------------------------------------------------------------------------
__global__ __launch_bounds__(256) void cvt_tf32_k(const float* __restrict__ in,
                                                  float* __restrict__ out)
{
    int i = blockIdx.x * 256 + threadIdx.x;      // float4 index
    float4 v = ((const float4*)in)[i];
    const int col0 = (i & (EMB / 4 - 1)) * 4;    // logical col of v.x
    const size_t rowbase = (size_t)(i / (EMB / 4)) * EMB;
    out[rowbase + perm8(col0 + 0)] = to_tf32(v.x);
    out[rowbase + perm8(col0 + 1)] = to_tf32(v.y);
    out[rowbase + perm8(col0 + 2)] = to_tf32(v.z);
    out[rowbase + perm8(col0 + 3)] = to_tf32(v.w);
}

// ---------------------------------------------------------------------------
// Fused weight transpose (4 weights via grid.z): WT[n][perm8(k)] = tf32(W[k][n])
// ---------------------------------------------------------------------------
__global__ __launch_bounds__(256) void transpose4_k(const float* __restrict__ W0,
                                                    const float* __restrict__ W1,
                                                    const float* __restrict__ W2,
                                                    const float* __restrict__ W3,
                                                    float* __restrict__ WTbase)
{
    const float* W;
    switch (blockIdx.z) {
        case 0: W = W0; break;
        case 1: W = W1; break;
        case 2: W = W2; break;
        default: W = W3; break;
    }
    float* WT = WTbase + (size_t)blockIdx.z * EMB * EMB;

    __shared__ float t[32][33];
    const int bx = blockIdx.x * 32, by = blockIdx.y * 32;
#pragma unroll
    for (int i = threadIdx.y; i < 32; i += 8)
        t[i][threadIdx.x] = W[(size_t)(by + i) * EMB + bx + threadIdx.x];
    __syncthreads();
#pragma unroll
    for (int i = threadIdx.y; i < 32; i += 8)
        WT[(size_t)(bx + i) * EMB + perm8(by + threadIdx.x)] = to_tf32(t[threadIdx.x][i]);
}

// ---------------------------------------------------------------------------
// mma.sync tf32 GEMM: C[M,N] = A[M,K] @ BT[N,K]^T; k-axis of A and BT is
// perm8-stored, so fragment pairs (k, k+4) load as one LDS.64.
// CTA 128x128, BK=32, 256 threads (8 warps 2x4), warp tile 64x32.
// MODE 0: C[row*N+col] = acc + bias[col]                 (natural cols)
// MODE 1: headsplit [B,H,S,D], tf32-rounded, d perm8'd   (Q, K)
// MODE 2: headsplit [B,H,S,D], tf32-rounded, d natural   (V)
// ---------------------------------------------------------------------------
#define GK_STRIDE 36
#define GK_TILE   (128 * GK_STRIDE * 4)
#define GK_SMEM   (4 * GK_TILE)

template <int MODE>
__global__ __launch_bounds__(256, 1) void gemm_tc(const float* __restrict__ A,
                                                  const float* __restrict__ BT,
                                                  const float* __restrict__ bias,
                                                  float* __restrict__ C)
{
    extern __shared__ char smem[];
    const uint32_t smem_base = smem_u32(smem);
    const int tid = threadIdx.x;
    const int wid = tid >> 5;
    const int lane = tid & 31;
    const int grp = lane >> 2;
    const int tig = lane & 3;
    const int bm = blockIdx.y * 128;
    const int bn = blockIdx.x * 128;
    const int wm = (wid >> 2) * 64;
    const int wn = (wid & 3) * 32;

    float acc[4][4][4];
#pragma unroll
    for (int mi = 0; mi < 4; mi++)
#pragma unroll
        for (int ni = 0; ni < 4; ni++)
#pragma unroll
            for (int r = 0; r < 4; r++) acc[mi][ni][r] = 0.f;

    const int crow = tid >> 1;
    const int cq   = (tid & 1) << 1;

    auto prefetch = [&](int c) {
        const int k0 = c * 32;
        const uint32_t sa = smem_base + (uint32_t)(c & 1) * GK_TILE;
        const uint32_t sb = smem_base + (uint32_t)(2 + (c & 1)) * GK_TILE;
#pragma unroll
        for (int h = 0; h < 2; h++) {
            int q0 = cq + h * 4;
            CP_ASYNC16(sa + (uint32_t)(crow * GK_STRIDE + q0 * 4) * 4,
                       A + (size_t)(bm + crow) * EMB + k0 + q0 * 4);
            CP_ASYNC16(sa + (uint32_t)(crow * GK_STRIDE + (q0 + 1) * 4) * 4,
                       A + (size_t)(bm + crow) * EMB + k0 + (q0 + 1) * 4);
        }
#pragma unroll
        for (int h = 0; h < 2; h++) {
            int q0 = cq + h * 4;
            CP_ASYNC16(sb + (uint32_t)(crow * GK_STRIDE + q0 * 4) * 4,
                       BT + (size_t)(bn + crow) * EMB + k0 + q0 * 4);
            CP_ASYNC16(sb + (uint32_t)(crow * GK_STRIDE + (q0 + 1) * 4) * 4,
                       BT + (size_t)(bn + crow) * EMB + k0 + (q0 + 1) * 4);
        }
        CP_COMMIT();
    };

    prefetch(0);

    for (int c = 0; c < 32; ++c) {
        if (c < 31) { prefetch(c + 1); CP_WAIT(1); }
        else        { CP_WAIT(0); }
        __syncthreads();

        const float* as = (const float*)(smem + (size_t)(c & 1) * GK_TILE);
        const float* bs = (const float*)(smem + (size_t)(2 + (c & 1)) * GK_TILE);

#pragma unroll
        for (int kk = 0; kk < 4; kk++) {
            const int kb = kk * 8 + 2 * tig;   // physical: pair (k, k+4)
            uint32_t af[4][4], bf[4][2];
#pragma unroll
            for (int mi = 0; mi < 4; mi++) {
                const float* p = as + (wm + mi * 16 + grp) * GK_STRIDE + kb;
                float2 u = *(const float2*)p;
                float2 w = *(const float2*)(p + 8 * GK_STRIDE);
                af[mi][0] = __float_as_uint(u.x);
                af[mi][2] = __float_as_uint(u.y);
                af[mi][1] = __float_as_uint(w.x);
                af[mi][3] = __float_as_uint(w.y);
            }
#pragma unroll
            for (int ni = 0; ni < 4; ni++) {
                float2 u = *(const float2*)(bs + (wn + ni * 8 + grp) * GK_STRIDE + kb);
                bf[ni][0] = __float_as_uint(u.x);
                bf[ni][1] = __float_as_uint(u.y);
            }
#pragma unroll
            for (int mi = 0; mi < 4; mi++)
#pragma unroll
                for (int ni = 0; ni < 4; ni++)
                    mma1688(acc[mi][ni], af[mi], bf[ni]);
        }
        __syncthreads();
    }

#pragma unroll
    for (int mi = 0; mi < 4; mi++) {
#pragma unroll
        for (int half = 0; half < 2; half++) {
            const int row = bm + wm + mi * 16 + grp + half * 8;
            if (MODE == 0) {
#pragma unroll
                for (int ni = 0; ni < 4; ni++) {
                    const int col = bn + wn + ni * 8 + tig * 2;
                    float2 v;
                    v.x = acc[mi][ni][half * 2 + 0] + bias[col + 0];
                    v.y = acc[mi][ni][half * 2 + 1] + bias[col + 1];
                    *(float2*)&C[(size_t)row * EMB + col] = v;
                }
            } else {
                const int b_ = row >> 11;
                const int sr = row & (S_LEN - 1);
#pragma unroll
                for (int ni = 0; ni < 4; ni++) {
                    const int col = bn + wn + ni * 8 + tig * 2;
                    const int h = col >> 6;
                    const int d = col & (HD - 1);
                    float* base = C + ((((size_t)b_ * NH + h) * S_LEN) + sr) * HD;
                    if (MODE == 1) {
                        base[perm8(d)]     = to_tf32(acc[mi][ni][half * 2 + 0]);
                        base[perm8(d + 1)] = to_tf32(acc[mi][ni][half * 2 + 1]);
                    } else {
                        float2 v;
                        v.x = to_tf32(acc[mi][ni][half * 2 + 0]);
                        v.y = to_tf32(acc[mi][ni][half * 2 + 1]);
                        *(float2*)(base + d) = v;
                    }
                }
            }
        }
    }
}

// ---------------------------------------------------------------------------
// Tensor-core flash attention (causal), tf32 mma.sync.
// Q/K stored head-dim perm8'd -> QK fragment pairs load as LDS.64.
// Block: 64 q-rows, 4 warps, 128 threads. 64-key tiles, cp.async dbl-buffered.
// Heavy blocks (large qb) launch first: qb = gridDim.x-1-blockIdx.x.
// ---------------------------------------------------------------------------
#define FS        68
#define FH_VS_OFF (2 * 64 * FS)
#define FH_PS_OFF (4 * 64 * FS)
#define FH_SMEM_BYTES ((FH_PS_OFF + 64 * FS) * 4)   // 87040

__global__ __launch_bounds__(128, 1) void flash_tc(const float* __restrict__ Q,
                                                   const float* __restrict__ Kg,
                                                   const float* __restrict__ Vg,
                                                   float* __restrict__ O)
{
    extern __shared__ float sm[];
    float* Ksm = sm;
    float* Vsm = sm + FH_VS_OFF;
    float* Psm = sm + FH_PS_OFF;   // also Q staging

    const int tid = threadIdx.x;
    const int wid = tid >> 5;
    const int lane = tid & 31;
    const int grp = lane >> 2;
    const int tig = lane & 3;
    const int qb = gridDim.x - 1 - blockIdx.x;   // heavy tiles first
    const int bh = blockIdx.y;

    const float* Qg = Q + ((size_t)bh * S_LEN + qb * 64) * HD;
    const float* Kb = Kg + (size_t)bh * S_LEN * HD;
    const float* Vb = Vg + (size_t)bh * S_LEN * HD;

    // Stage Q (64x64, already dim-permuted) into Psm, pre-scaled by 0.125
    for (int i = tid; i < 64 * 16; i += 128) {
        int row = i >> 4, f4 = i & 15;
        float4 v = ((const float4*)(Qg + (size_t)row * HD))[f4];
        v.x *= 0.125f; v.y *= 0.125f; v.z *= 0.125f; v.w *= 0.125f;
        *(float4*)&Psm[row * FS + f4 * 4] = v;
    }
    __syncthreads();

    // Q fragments: pairs (k, k+4) are physically adjacent -> float2 loads
    uint32_t qf[8][4];
    {
        const float* qw = Psm + (wid * 16) * FS;
#pragma unroll
        for (int ks = 0; ks < 8; ks++) {
            float2 a = *(const float2*)&qw[grp * FS + ks * 8 + 2 * tig];
            float2 b = *(const float2*)&qw[(grp + 8) * FS + ks * 8 + 2 * tig];
            qf[ks][0] = __float_as_uint(a.x);
            qf[ks][2] = __float_as_uint(a.y);
            qf[ks][1] = __float_as_uint(b.x);
            qf[ks][3] = __float_as_uint(b.y);
        }
    }
    __syncthreads();   // Psm now free for P tiles

    float acc[8][4];
#pragma unroll
    for (int n = 0; n < 8; n++)
#pragma unroll
        for (int r = 0; r < 4; r++) acc[n][r] = 0.f;
    float m_lo = -1e30f, m_hi = -1e30f, l_lo = 0.f, l_hi = 0.f;

    const int crow = tid >> 1;
    const int chf  = (tid & 1) * 8;

    auto prefetch = [&](int kt) {
        const int st = kt & 1;
        const float* ksrc = Kb + (size_t)(kt * 64 + crow) * HD;
        const float* vsrc = Vb + (size_t)(kt * 64 + crow) * HD;
        uint32_t kd = smem_u32(Ksm + (size_t)st * 64 * FS + crow * FS);
        uint32_t vd = smem_u32(Vsm + (size_t)st * 64 * FS + crow * FS);
#pragma unroll
        for (int j = 0; j < 8; j++) {
            int f4 = chf + j;
            CP_ASYNC16(kd + (uint32_t)f4 * 16, ksrc + f4 * 4);
            CP_ASYNC16(vd + (uint32_t)f4 * 16, vsrc + f4 * 4);
        }
        CP_COMMIT();
    };

    const int nt = qb + 1;
    prefetch(0);

    for (int kt = 0; kt < nt; kt++) {
        if (kt + 1 < nt) { prefetch(kt + 1); CP_WAIT(1); }
        else             { CP_WAIT(0); }
        __syncthreads();

        const float* ks_ = Ksm + (size_t)(kt & 1) * 64 * FS;
        const float* vs_ = Vsm + (size_t)(kt & 1) * 64 * FS;

        // --- scores S = Q K^T (pre-scaled); K dim-permuted -> float2 B-frags
        float c[8][4];
#pragma unroll
        for (int n = 0; n < 8; n++) {
#pragma unroll
            for (int r = 0; r < 4; r++) c[n][r] = 0.f;
            const float* kp = ks_ + (n * 8 + grp) * FS;
#pragma unroll
            for (int ks = 0; ks < 8; ks++) {
                float2 kk = *(const float2*)&kp[ks * 8 + 2 * tig];
                uint32_t bf[2];
                bf[0] = __float_as_uint(kk.x);
                bf[1] = __float_as_uint(kk.y);
                mma1688(c[n], qf[ks], bf);
            }
        }

        // --- causal mask (diagonal block only) ---
        if (kt == qb) {
            const int r0 = wid * 16 + grp, r1 = r0 + 8;
#pragma unroll
            for (int n = 0; n < 8; n++) {
                const int cl = n * 8 + 2 * tig;
                if (cl     > r0) c[n][0] = -1e30f;
                if (cl + 1 > r0) c[n][1] = -1e30f;
                if (cl     > r1) c[n][2] = -1e30f;
                if (cl + 1 > r1) c[n][3] = -1e30f;
            }
        }

        // --- online softmax ---
        float tmx_lo = -1e30f, tmx_hi = -1e30f;
#pragma unroll
        for (int n = 0; n < 8; n++) {
            tmx_lo = fmaxf(tmx_lo, fmaxf(c[n][0], c[n][1]));
            tmx_hi = fmaxf(tmx_hi, fmaxf(c[n][2], c[n][3]));
        }
        tmx_lo = fmaxf(tmx_lo, __shfl_xor_sync(0xFFFFFFFF, tmx_lo, 1));
        tmx_lo = fmaxf(tmx_lo, __shfl_xor_sync(0xFFFFFFFF, tmx_lo, 2));
        tmx_hi = fmaxf(tmx_hi, __shfl_xor_sync(0xFFFFFFFF, tmx_hi, 1));
        tmx_hi = fmaxf(tmx_hi, __shfl_xor_sync(0xFFFFFFFF, tmx_hi, 2));

        const float mn_lo = fmaxf(m_lo, tmx_lo);
        const float mn_hi = fmaxf(m_hi, tmx_hi);
        const float corr_lo = __expf(m_lo - mn_lo);
        const float corr_hi = __expf(m_hi - mn_hi);

        float sum_lo = 0.f, sum_hi = 0.f;
#pragma unroll
        for (int n = 0; n < 8; n++) {
            c[n][0] = __expf(c[n][0] - mn_lo);
            c[n][1] = __expf(c[n][1] - mn_lo);
            c[n][2] = __expf(c[n][2] - mn_hi);
            c[n][3] = __expf(c[n][3] - mn_hi);
            sum_lo += c[n][0] + c[n][1];
            sum_hi += c[n][2] + c[n][3];
        }
        sum_lo += __shfl_xor_sync(0xFFFFFFFF, sum_lo, 1);
        sum_lo += __shfl_xor_sync(0xFFFFFFFF, sum_lo, 2);
        sum_hi += __shfl_xor_sync(0xFFFFFFFF, sum_hi, 1);
        sum_hi += __shfl_xor_sync(0xFFFFFFFF, sum_hi, 2);

        l_lo = l_lo * corr_lo + sum_lo;
        l_hi = l_hi * corr_hi + sum_hi;
        m_lo = mn_lo; m_hi = mn_hi;

#pragma unroll
        for (int n = 0; n < 8; n++) {
            acc[n][0] *= corr_lo; acc[n][1] *= corr_lo;
            acc[n][2] *= corr_hi; acc[n][3] *= corr_hi;
        }

        // --- P -> per-warp SMEM (tf32-rounded), reload as A-frags ---
        float* pw = Psm + wid * 16 * FS;
#pragma unroll
        for (int n = 0; n < 8; n++) {
            float2 lo, hi;
            lo.x = to_tf32(c[n][0]); lo.y = to_tf32(c[n][1]);
            hi.x = to_tf32(c[n][2]); hi.y = to_tf32(c[n][3]);
            *(float2*)&pw[grp * FS + n * 8 + 2 * tig] = lo;
            *(float2*)&pw[(grp + 8) * FS + n * 8 + 2 * tig] = hi;
        }
        __syncwarp();

        // --- PV: acc += P @ V (V natural; contraction over keys) ---
#pragma unroll
        for (int ks = 0; ks < 8; ks++) {
            uint32_t pa[4];
            pa[0] = __float_as_uint(pw[grp * FS + ks * 8 + tig]);
            pa[1] = __float_as_uint(pw[(grp + 8) * FS + ks * 8 + tig]);
            pa[2] = __float_as_uint(pw[grp * FS + ks * 8 + tig + 4]);
            pa[3] = __float_as_uint(pw[(grp + 8) * FS + ks * 8 + tig + 4]);
            const float* v0 = vs_ + (ks * 8 + tig) * FS;
            const float* v1 = vs_ + (ks * 8 + tig + 4) * FS;
#pragma unroll
            for (int nd = 0; nd < 8; nd++) {
                uint32_t bf[2];
                bf[0] = __float_as_uint(v0[nd * 8 + grp]);
                bf[1] = __float_as_uint(v1[nd * 8 + grp]);
                mma1688(acc[nd], pa, bf);
            }
        }
        __syncthreads();
    }

    // --- epilogue: normalize, write ctx [B,S,E], e-dim perm8'd for MODE0 gemm
    const float inv_lo = 1.f / l_lo;
    const float inv_hi = 1.f / l_hi;
    const int b_ = bh >> 4;
    const int h  = bh & 15;
    const int r_lo = qb * 64 + wid * 16 + grp;
    const int r_hi = r_lo + 8;
    float* olo = O + ((size_t)b_ * S_LEN + r_lo) * EMB + h * HD;
    float* ohi = O + ((size_t)b_ * S_LEN + r_hi) * EMB + h * HD;
#pragma unroll
    for (int nd = 0; nd < 8; nd++) {
        const int col = nd * 8 + 2 * tig;
        const int c0 = perm8(col);
        const int c1 = perm8(col + 1);
        olo[c0] = to_tf32(acc[nd][0] * inv_lo);
        olo[c1] = to_tf32(acc[nd][1] * inv_lo);
        ohi[c0] = to_tf32(acc[nd][2] * inv_hi);
        ohi[c1] = to_tf32(acc[nd][3] * inv_hi);
    }
}

// ---------------------------------------------------------------------------
extern "C" void kernel_launch(void* const* d_in, const int* in_sizes, int n_in,
                              void* d_out, int out_size)
{
    const float* x  = (const float*)d_in[0];
    const float* Wq = (const float*)d_in[1];
    const float* Wk = (const float*)d_in[2];
    const float* Wv = (const float*)d_in[3];
    const float* Wo = (const float*)d_in[4];
    const float* bo = (const float*)d_in[5];
    float* out = (float*)d_out;

    float *qb, *kb, *vb, *cb, *xt, *wt;
    cudaGetSymbolAddress((void**)&qb, g_q);
    cudaGetSymbolAddress((void**)&kb, g_k);
    cudaGetSymbolAddress((void**)&vb, g_v);
    cudaGetSymbolAddress((void**)&cb, g_ctx);
    cudaGetSymbolAddress((void**)&xt, g_xt);
    cudaGetSymbolAddress((void**)&wt, g_wt);
    float* wtq = wt + 0ULL * EMB * EMB;
    float* wtk = wt + 1ULL * EMB * EMB;
    float* wtv = wt + 2ULL * EMB * EMB;
    float* wto = wt + 3ULL * EMB * EMB;

    cudaFuncSetAttribute(gemm_tc<0>, cudaFuncAttributeMaxDynamicSharedMemorySize, GK_SMEM);
    cudaFuncSetAttribute(gemm_tc<1>, cudaFuncAttributeMaxDynamicSharedMemorySize, GK_SMEM);
    cudaFuncSetAttribute(gemm_tc<2>, cudaFuncAttributeMaxDynamicSharedMemorySize, GK_SMEM);
    cudaFuncSetAttribute(flash_tc, cudaFuncAttributeMaxDynamicSharedMemorySize, FH_SMEM_BYTES);

    cvt_tf32_k<<<(MROWS * EMB / 4) / 256, 256>>>(x, xt);
    transpose4_k<<<dim3(EMB / 32, EMB / 32, 4), dim3(32, 8)>>>(Wq, Wk, Wv, Wo, wt);

    dim3 gg(EMB / 128, MROWS / 128);  // (8, 32)
    gemm_tc<1><<<gg, 256, GK_SMEM>>>(xt, wtq, nullptr, qb);
    gemm_tc<1><<<gg, 256, GK_SMEM>>>(xt, wtk, nullptr, kb);
    gemm_tc<2><<<gg, 256, GK_SMEM>>>(xt, wtv, nullptr, vb);

    flash_tc<<<dim3(S_LEN / 64, BATCH * NH), 128, FH_SMEM_BYTES>>>(qb, kb, vb, cb);

    gemm_tc<0><<<gg, 256, GK_SMEM>>>(cb, wto, bo, out);
}

// round 17
// speedup vs baseline: 1.2085x; 1.2085x over previous
#include <cuda_runtime.h>
#include <cuda_bf16.h>
#include <cstdint>
#include <cstddef>

// Problem constants
#define S_LEN  2048
#define EMB    1024
#define NH     16
#define HD     64
#define BATCH  2
#define MROWS  (BATCH * S_LEN)   // 4096

// Scratch in device globals (no allocation allowed)
__device__ float g_q[(size_t)BATCH * NH * S_LEN * HD];     // head-dim perm8'd
__device__ float g_k[(size_t)BATCH * NH * S_LEN * HD];     // head-dim perm8'd
__device__ float g_v[(size_t)BATCH * NH * S_LEN * HD];     // natural
__device__ float g_ctx[(size_t)BATCH * S_LEN * EMB];       // e-dim perm8'd
__device__ float g_xt[(size_t)MROWS * EMB];                // tf32, e-dim perm8'd
__device__ float g_wt[4ULL * EMB * EMB];                   // transposed, tf32, k perm8'd

// ---------------------------------------------------------------------------
// Helpers
// ---------------------------------------------------------------------------
__device__ __forceinline__ uint32_t smem_u32(const void* p) {
    uint32_t a;
    asm("{ .reg .u64 t; cvta.to.shared.u64 t, %1; cvt.u32.u64 %0, t; }" : "=r"(a) : "l"(p));
    return a;
}
__device__ __forceinline__ float to_tf32(float x) {
    float y;
    asm("cvt.rna.tf32.f32 %0, %1;" : "=f"(y) : "f"(x));
    return y;
}
// permutation of the contraction axis within 8-blocks: logical j -> physical p
// p(j) = 2*(j&3) + (j>>2)  => pairs (j, j+4) become physically adjacent
__device__ __forceinline__ int perm8(int d) {
    return (d & ~7) | (2 * (d & 3) + ((d >> 2) & 1));
}

#define CP_ASYNC16(sa, gp) \
    asm volatile("cp.async.cg.shared.global [%0], [%1], 16;" :: "r"(sa), "l"(gp) : "memory")
#define CP_COMMIT() asm volatile("cp.async.commit_group;" ::: "memory")
#define CP_WAIT(n)  asm volatile("cp.async.wait_group %0;" :: "n"(n) : "memory")

// m16n8k8 tf32 mma: D += A * B  (A row-major m16k8 frag, B col-major n8k8 frag)
__device__ __forceinline__ void mma1688(float* c, const uint32_t* a, const uint32_t* b) {
    asm volatile(
        "mma.sync.aligned.m16n8k8.row.col.f32.tf32.tf32.f32 "
        "{%0,%1,%2,%3}, {%4,%5,%6,%7}, {%8,%9}, {%0,%1,%2,%3};"
        : "+f"(c[0]), "+f"(c[1]), "+f"(c[2]), "+f"(c[3])
        : "r"(a[0]), "r"(a[1]), "r"(a[2]), "r"(a[3]), "r"(b[0]), "r"(b[1]));
}

// ---------------------------------------------------------------------------
// x -> tf32-rounded copy with e-dim permutation
// ---------------------------------------------------------------------------
__global__ __launch_bounds__(256) void cvt_tf32_k(const float* __restrict__ in,
                                                  float* __restrict__ out)
{
    int i = blockIdx.x * 256 + threadIdx.x;      // float4 index
    float4 v = ((const float4*)in)[i];
    const int col0 = (i & (EMB / 4 - 1)) * 4;
    const size_t rowbase = (size_t)(i / (EMB / 4)) * EMB;
    out[rowbase + perm8(col0 + 0)] = to_tf32(v.x);
    out[rowbase + perm8(col0 + 1)] = to_tf32(v.y);
    out[rowbase + perm8(col0 + 2)] = to_tf32(v.z);
    out[rowbase + perm8(col0 + 3)] = to_tf32(v.w);
}

// ---------------------------------------------------------------------------
// Fused weight transpose (4 weights via grid.z): WT[n][perm8(k)] = tf32(W[k][n])
// ---------------------------------------------------------------------------
__global__ __launch_bounds__(256) void transpose4_k(const float* __restrict__ W0,
                                                    const float* __restrict__ W1,
                                                    const float* __restrict__ W2,
                                                    const float* __restrict__ W3,
                                                    float* __restrict__ WTbase)
{
    const float* W;
    switch (blockIdx.z) {
        case 0: W = W0; break;
        case 1: W = W1; break;
        case 2: W = W2; break;
        default: W = W3; break;
    }
    float* WT = WTbase + (size_t)blockIdx.z * EMB * EMB;

    __shared__ float t[32][33];
    const int bx = blockIdx.x * 32, by = blockIdx.y * 32;
#pragma unroll
    for (int i = threadIdx.y; i < 32; i += 8)
        t[i][threadIdx.x] = W[(size_t)(by + i) * EMB + bx + threadIdx.x];
    __syncthreads();
#pragma unroll
    for (int i = threadIdx.y; i < 32; i += 8)
        WT[(size_t)(bx + i) * EMB + perm8(by + threadIdx.x)] = to_tf32(t[threadIdx.x][i]);
}

// ---------------------------------------------------------------------------
// mma.sync tf32 GEMM core: C[M,N] = A[M,K] @ BT[N,K]^T; k-axes perm8-stored
// so fragment pairs (k, k+4) load as one LDS.64 (stride 40 -> conflict-free).
// CTA 128x128, BK=32, 256 threads (8 warps 2x4), warp tile 64x32.
// Software-pipelined kk loop (double-buffered fragment registers).
// mode 0: C[row*N+col] = acc + bias[col]                 (natural cols)
// mode 1: headsplit [B,H,S,D], tf32-rounded, d perm8'd   (Q, K)
// mode 2: headsplit [B,H,S,D], tf32-rounded, d natural   (V)
// ---------------------------------------------------------------------------
#define GK_STRIDE 40
#define GK_TILE   (128 * GK_STRIDE * 4)    // 20480 bytes
#define GK_SMEM   (4 * GK_TILE)            // 81920

__device__ __forceinline__ void gemm_core(const float* __restrict__ A,
                                          const float* __restrict__ BT,
                                          const float* __restrict__ bias,
                                          float* __restrict__ C,
                                          int mode, char* smem)
{
    const uint32_t smem_base = smem_u32(smem);
    const int tid = threadIdx.x;
    const int wid = tid >> 5;
    const int lane = tid & 31;
    const int grp = lane >> 2;
    const int tig = lane & 3;
    const int bm = blockIdx.y * 128;
    const int bn = blockIdx.x * 128;
    const int wm = (wid >> 2) * 64;
    const int wn = (wid & 3) * 32;

    float acc[4][4][4];
#pragma unroll
    for (int mi = 0; mi < 4; mi++)
#pragma unroll
        for (int ni = 0; ni < 4; ni++)
#pragma unroll
            for (int r = 0; r < 4; r++) acc[mi][ni][r] = 0.f;

    const int crow = tid >> 1;
    const int cq   = (tid & 1) << 1;

    auto prefetch = [&](int c) {
        const int k0 = c * 32;
        const uint32_t sa = smem_base + (uint32_t)(c & 1) * GK_TILE;
        const uint32_t sb = smem_base + (uint32_t)(2 + (c & 1)) * GK_TILE;
#pragma unroll
        for (int h = 0; h < 2; h++) {
            int q0 = cq + h * 4;
            CP_ASYNC16(sa + (uint32_t)(crow * GK_STRIDE + q0 * 4) * 4,
                       A + (size_t)(bm + crow) * EMB + k0 + q0 * 4);
            CP_ASYNC16(sa + (uint32_t)(crow * GK_STRIDE + (q0 + 1) * 4) * 4,
                       A + (size_t)(bm + crow) * EMB + k0 + (q0 + 1) * 4);
        }
#pragma unroll
        for (int h = 0; h < 2; h++) {
            int q0 = cq + h * 4;
            CP_ASYNC16(sb + (uint32_t)(crow * GK_STRIDE + q0 * 4) * 4,
                       BT + (size_t)(bn + crow) * EMB + k0 + q0 * 4);
            CP_ASYNC16(sb + (uint32_t)(crow * GK_STRIDE + (q0 + 1) * 4) * 4,
                       BT + (size_t)(bn + crow) * EMB + k0 + (q0 + 1) * 4);
        }
        CP_COMMIT();
    };

    prefetch(0);

    for (int c = 0; c < 32; ++c) {
        if (c < 31) { prefetch(c + 1); CP_WAIT(1); }
        else        { CP_WAIT(0); }
        __syncthreads();

        const float* as = (const float*)(smem + (size_t)(c & 1) * GK_TILE);
        const float* bs = (const float*)(smem + (size_t)(2 + (c & 1)) * GK_TILE);

        uint32_t af[2][4][4], bf[2][4][2];

        // fragment load for one kk into buffer u
#define LOAD_FRAGS(kk, u)                                                        \
        do {                                                                     \
            const int kb_ = (kk) * 8 + 2 * tig;                                  \
            _Pragma("unroll")                                                    \
            for (int mi = 0; mi < 4; mi++) {                                     \
                const float* p = as + (wm + mi * 16 + grp) * GK_STRIDE + kb_;    \
                float2 u0 = *(const float2*)p;                                   \
                float2 u1 = *(const float2*)(p + 8 * GK_STRIDE);                 \
                af[u][mi][0] = __float_as_uint(u0.x);                            \
                af[u][mi][2] = __float_as_uint(u0.y);                            \
                af[u][mi][1] = __float_as_uint(u1.x);                            \
                af[u][mi][3] = __float_as_uint(u1.y);                            \
            }                                                                    \
            _Pragma("unroll")                                                    \
            for (int ni = 0; ni < 4; ni++) {                                     \
                float2 u0 = *(const float2*)(bs + (wn + ni * 8 + grp) * GK_STRIDE + kb_); \
                bf[u][ni][0] = __float_as_uint(u0.x);                            \
                bf[u][ni][1] = __float_as_uint(u0.y);                            \
            }                                                                    \
        } while (0)

        LOAD_FRAGS(0, 0);
#pragma unroll
        for (int kk = 0; kk < 4; kk++) {
            if (kk < 3) {
                if ((kk & 1) == 0) LOAD_FRAGS(kk + 1, 1);
                else               LOAD_FRAGS(kk + 1, 0);
            }
            const int u = kk & 1;
#pragma unroll
            for (int mi = 0; mi < 4; mi++)
#pragma unroll
                for (int ni = 0; ni < 4; ni++)
                    mma1688(acc[mi][ni], af[u][mi], bf[u][ni]);
        }
#undef LOAD_FRAGS
        __syncthreads();
    }

#pragma unroll
    for (int mi = 0; mi < 4; mi++) {
#pragma unroll
        for (int half = 0; half < 2; half++) {
            const int row = bm + wm + mi * 16 + grp + half * 8;
            if (mode == 0) {
#pragma unroll
                for (int ni = 0; ni < 4; ni++) {
                    const int col = bn + wn + ni * 8 + tig * 2;
                    float2 v;
                    v.x = acc[mi][ni][half * 2 + 0] + bias[col + 0];
                    v.y = acc[mi][ni][half * 2 + 1] + bias[col + 1];
                    *(float2*)&C[(size_t)row * EMB + col] = v;
                }
            } else {
                const int b_ = row >> 11;
                const int sr = row & (S_LEN - 1);
#pragma unroll
                for (int ni = 0; ni < 4; ni++) {
                    const int col = bn + wn + ni * 8 + tig * 2;
                    const int h = col >> 6;
                    const int d = col & (HD - 1);
                    float* base = C + ((((size_t)b_ * NH + h) * S_LEN) + sr) * HD;
                    if (mode == 1) {
                        base[perm8(d)]     = to_tf32(acc[mi][ni][half * 2 + 0]);
                        base[perm8(d + 1)] = to_tf32(acc[mi][ni][half * 2 + 1]);
                    } else {
                        float2 v;
                        v.x = to_tf32(acc[mi][ni][half * 2 + 0]);
                        v.y = to_tf32(acc[mi][ni][half * 2 + 1]);
                        *(float2*)(base + d) = v;
                    }
                }
            }
        }
    }
}

// Fused Q/K/V projection: grid.z selects weight + destination.
__global__ __launch_bounds__(256, 1) void gemm_qkv(const float* __restrict__ A,
                                                   const float* __restrict__ WTbase,
                                                   float* __restrict__ Qd,
                                                   float* __restrict__ Kd,
                                                   float* __restrict__ Vd)
{
    extern __shared__ char smem[];
    const int z = blockIdx.z;
    const float* BT = WTbase + (size_t)z * EMB * EMB;
    float* C = (z == 0) ? Qd : (z == 1) ? Kd : Vd;
    gemm_core(A, BT, nullptr, C, (z == 2) ? 2 : 1, smem);
}

// Output projection (mode 0)
__global__ __launch_bounds__(256, 1) void gemm_out(const float* __restrict__ A,
                                                   const float* __restrict__ BT,
                                                   const float* __restrict__ bias,
                                                   float* __restrict__ C)
{
    extern __shared__ char smem[];
    gemm_core(A, BT, bias, C, 0, smem);
}

// ---------------------------------------------------------------------------
// Tensor-core flash attention (causal), tf32 mma.sync.
// Q/K stored head-dim perm8'd -> QK fragment pairs load as LDS.64.
// FS=72 (==8 mod 32) -> conflict-free float2 B-frags AND PV V-loads.
// Block: 64 q-rows, 4 warps, 128 threads. 64-key tiles, cp.async dbl-buffered.
// Heavy blocks (large qb) launch first.
// ---------------------------------------------------------------------------
#define FS        72
#define FH_VS_OFF (2 * 64 * FS)
#define FH_PS_OFF (4 * 64 * FS)
#define FH_SMEM_BYTES ((FH_PS_OFF + 64 * FS) * 4)   // 92160

__global__ __launch_bounds__(128, 1) void flash_tc(const float* __restrict__ Q,
                                                   const float* __restrict__ Kg,
                                                   const float* __restrict__ Vg,
                                                   float* __restrict__ O)
{
    extern __shared__ float sm[];
    float* Ksm = sm;
    float* Vsm = sm + FH_VS_OFF;
    float* Psm = sm + FH_PS_OFF;   // also Q staging

    const int tid = threadIdx.x;
    const int wid = tid >> 5;
    const int lane = tid & 31;
    const int grp = lane >> 2;
    const int tig = lane & 3;
    const int qb = gridDim.x - 1 - blockIdx.x;   // heavy tiles first
    const int bh = blockIdx.y;

    const float* Qg = Q + ((size_t)bh * S_LEN + qb * 64) * HD;
    const float* Kb = Kg + (size_t)bh * S_LEN * HD;
    const float* Vb = Vg + (size_t)bh * S_LEN * HD;

    // Stage Q (64x64, already dim-permuted) into Psm, pre-scaled by 0.125
    for (int i = tid; i < 64 * 16; i += 128) {
        int row = i >> 4, f4 = i & 15;
        float4 v = ((const float4*)(Qg + (size_t)row * HD))[f4];
        v.x *= 0.125f; v.y *= 0.125f; v.z *= 0.125f; v.w *= 0.125f;
        *(float4*)&Psm[row * FS + f4 * 4] = v;
    }
    __syncthreads();

    // Q fragments: pairs (k, k+4) physically adjacent -> float2 loads
    uint32_t qf[8][4];
    {
        const float* qw = Psm + (wid * 16) * FS;
#pragma unroll
        for (int ks = 0; ks < 8; ks++) {
            float2 a = *(const float2*)&qw[grp * FS + ks * 8 + 2 * tig];
            float2 b = *(const float2*)&qw[(grp + 8) * FS + ks * 8 + 2 * tig];
            qf[ks][0] = __float_as_uint(a.x);
            qf[ks][2] = __float_as_uint(a.y);
            qf[ks][1] = __float_as_uint(b.x);
            qf[ks][3] = __float_as_uint(b.y);
        }
    }
    __syncthreads();   // Psm now free for P tiles

    float acc[8][4];
#pragma unroll
    for (int n = 0; n < 8; n++)
#pragma unroll
        for (int r = 0; r < 4; r++) acc[n][r] = 0.f;
    float m_lo = -1e30f, m_hi = -1e30f, l_lo = 0.f, l_hi = 0.f;

    const int crow = tid >> 1;
    const int chf  = (tid & 1) * 8;

    auto prefetch = [&](int kt) {
        const int st = kt & 1;
        const float* ksrc = Kb + (size_t)(kt * 64 + crow) * HD;
        const float* vsrc = Vb + (size_t)(kt * 64 + crow) * HD;
        uint32_t kd = smem_u32(Ksm + (size_t)st * 64 * FS + crow * FS);
        uint32_t vd = smem_u32(Vsm + (size_t)st * 64 * FS + crow * FS);
#pragma unroll
        for (int j = 0; j < 8; j++) {
            int f4 = chf + j;
            CP_ASYNC16(kd + (uint32_t)f4 * 16, ksrc + f4 * 4);
            CP_ASYNC16(vd + (uint32_t)f4 * 16, vsrc + f4 * 4);
        }
        CP_COMMIT();
    };

    const int nt = qb + 1;
    prefetch(0);

    for (int kt = 0; kt < nt; kt++) {
        if (kt + 1 < nt) { prefetch(kt + 1); CP_WAIT(1); }
        else             { CP_WAIT(0); }
        __syncthreads();

        const float* ks_ = Ksm + (size_t)(kt & 1) * 64 * FS;
        const float* vs_ = Vsm + (size_t)(kt & 1) * 64 * FS;

        // --- scores S = Q K^T (pre-scaled); K dim-permuted -> float2 B-frags
        float c[8][4];
#pragma unroll
        for (int n = 0; n < 8; n++) {
#pragma unroll
            for (int r = 0; r < 4; r++) c[n][r] = 0.f;
            const float* kp = ks_ + (n * 8 + grp) * FS;
#pragma unroll
            for (int ks = 0; ks < 8; ks++) {
                float2 kk = *(const float2*)&kp[ks * 8 + 2 * tig];
                uint32_t bf[2];
                bf[0] = __float_as_uint(kk.x);
                bf[1] = __float_as_uint(kk.y);
                mma1688(c[n], qf[ks], bf);
            }
        }

        // --- causal mask (diagonal block only) ---
        if (kt == qb) {
            const int r0 = wid * 16 + grp, r1 = r0 + 8;
#pragma unroll
            for (int n = 0; n < 8; n++) {
                const int cl = n * 8 + 2 * tig;
                if (cl     > r0) c[n][0] = -1e30f;
                if (cl + 1 > r0) c[n][1] = -1e30f;
                if (cl     > r1) c[n][2] = -1e30f;
                if (cl + 1 > r1) c[n][3] = -1e30f;
            }
        }

        // --- online softmax ---
        float tmx_lo = -1e30f, tmx_hi = -1e30f;
#pragma unroll
        for (int n = 0; n < 8; n++) {
            tmx_lo = fmaxf(tmx_lo, fmaxf(c[n][0], c[n][1]));
            tmx_hi = fmaxf(tmx_hi, fmaxf(c[n][2], c[n][3]));
        }
        tmx_lo = fmaxf(tmx_lo, __shfl_xor_sync(0xFFFFFFFF, tmx_lo, 1));
        tmx_lo = fmaxf(tmx_lo, __shfl_xor_sync(0xFFFFFFFF, tmx_lo, 2));
        tmx_hi = fmaxf(tmx_hi, __shfl_xor_sync(0xFFFFFFFF, tmx_hi, 1));
        tmx_hi = fmaxf(tmx_hi, __shfl_xor_sync(0xFFFFFFFF, tmx_hi, 2));

        const float mn_lo = fmaxf(m_lo, tmx_lo);
        const float mn_hi = fmaxf(m_hi, tmx_hi);
        const float corr_lo = __expf(m_lo - mn_lo);
        const float corr_hi = __expf(m_hi - mn_hi);

        float sum_lo = 0.f, sum_hi = 0.f;
#pragma unroll
        for (int n = 0; n < 8; n++) {
            c[n][0] = __expf(c[n][0] - mn_lo);
            c[n][1] = __expf(c[n][1] - mn_lo);
            c[n][2] = __expf(c[n][2] - mn_hi);
            c[n][3] = __expf(c[n][3] - mn_hi);
            sum_lo += c[n][0] + c[n][1];
            sum_hi += c[n][2] + c[n][3];
        }
        sum_lo += __shfl_xor_sync(0xFFFFFFFF, sum_lo, 1);
        sum_lo += __shfl_xor_sync(0xFFFFFFFF, sum_lo, 2);
        sum_hi += __shfl_xor_sync(0xFFFFFFFF, sum_hi, 1);
        sum_hi += __shfl_xor_sync(0xFFFFFFFF, sum_hi, 2);

        l_lo = l_lo * corr_lo + sum_lo;
        l_hi = l_hi * corr_hi + sum_hi;
        m_lo = mn_lo; m_hi = mn_hi;

#pragma unroll
        for (int n = 0; n < 8; n++) {
            acc[n][0] *= corr_lo; acc[n][1] *= corr_lo;
            acc[n][2] *= corr_hi; acc[n][3] *= corr_hi;
        }

        // --- P -> per-warp SMEM (tf32-rounded), reload as A-frags ---
        float* pw = Psm + wid * 16 * FS;
#pragma unroll
        for (int n = 0; n < 8; n++) {
            float2 lo, hi;
            lo.x = to_tf32(c[n][0]); lo.y = to_tf32(c[n][1]);
            hi.x = to_tf32(c[n][2]); hi.y = to_tf32(c[n][3]);
            *(float2*)&pw[grp * FS + n * 8 + 2 * tig] = lo;
            *(float2*)&pw[(grp + 8) * FS + n * 8 + 2 * tig] = hi;
        }
        __syncwarp();

        // --- PV: acc += P @ V (V natural; contraction over keys) ---
#pragma unroll
        for (int ks = 0; ks < 8; ks++) {
            uint32_t pa[4];
            pa[0] = __float_as_uint(pw[grp * FS + ks * 8 + tig]);
            pa[1] = __float_as_uint(pw[(grp + 8) * FS + ks * 8 + tig]);
            pa[2] = __float_as_uint(pw[grp * FS + ks * 8 + tig + 4]);
            pa[3] = __float_as_uint(pw[(grp + 8) * FS + ks * 8 + tig + 4]);
            const float* v0 = vs_ + (ks * 8 + tig) * FS;
            const float* v1 = vs_ + (ks * 8 + tig + 4) * FS;
#pragma unroll
            for (int nd = 0; nd < 8; nd++) {
                uint32_t bf[2];
                bf[0] = __float_as_uint(v0[nd * 8 + grp]);
                bf[1] = __float_as_uint(v1[nd * 8 + grp]);
                mma1688(acc[nd], pa, bf);
            }
        }
        __syncthreads();
    }

    // --- epilogue: normalize, write ctx [B,S,E], e-dim perm8'd for out-gemm
    const float inv_lo = 1.f / l_lo;
    const float inv_hi = 1.f / l_hi;
    const int b_ = bh >> 4;
    const int h  = bh & 15;
    const int r_lo = qb * 64 + wid * 16 + grp;
    const int r_hi = r_lo + 8;
    float* olo = O + ((size_t)b_ * S_LEN + r_lo) * EMB + h * HD;
    float* ohi = O + ((size_t)b_ * S_LEN + r_hi) * EMB + h * HD;
#pragma unroll
    for (int nd = 0; nd < 8; nd++) {
        const int col = nd * 8 + 2 * tig;
        const int c0 = perm8(col);
        const int c1 = perm8(col + 1);
        olo[c0] = to_tf32(acc[nd][0] * inv_lo);
        olo[c1] = to_tf32(acc[nd][1] * inv_lo);
        ohi[c0] = to_tf32(acc[nd][2] * inv_hi);
        ohi[c1] = to_tf32(acc[nd][3] * inv_hi);
    }
}

// ---------------------------------------------------------------------------
extern "C" void kernel_launch(void* const* d_in, const int* in_sizes, int n_in,
                              void* d_out, int out_size)
{
    const float* x  = (const float*)d_in[0];
    const float* Wq = (const float*)d_in[1];
    const float* Wk = (const float*)d_in[2];
    const float* Wv = (const float*)d_in[3];
    const float* Wo = (const float*)d_in[4];
    const float* bo = (const float*)d_in[5];
    float* out = (float*)d_out;

    float *qb, *kb, *vb, *cb, *xt, *wt;
    cudaGetSymbolAddress((void**)&qb, g_q);
    cudaGetSymbolAddress((void**)&kb, g_k);
    cudaGetSymbolAddress((void**)&vb, g_v);
    cudaGetSymbolAddress((void**)&cb, g_ctx);
    cudaGetSymbolAddress((void**)&xt, g_xt);
    cudaGetSymbolAddress((void**)&wt, g_wt);
    float* wto = wt + 3ULL * EMB * EMB;

    cudaFuncSetAttribute(gemm_qkv, cudaFuncAttributeMaxDynamicSharedMemorySize, GK_SMEM);
    cudaFuncSetAttribute(gemm_out, cudaFuncAttributeMaxDynamicSharedMemorySize, GK_SMEM);
    cudaFuncSetAttribute(flash_tc, cudaFuncAttributeMaxDynamicSharedMemorySize, FH_SMEM_BYTES);

    cvt_tf32_k<<<(MROWS * EMB / 4) / 256, 256>>>(x, xt);
    transpose4_k<<<dim3(EMB / 32, EMB / 32, 4), dim3(32, 8)>>>(Wq, Wk, Wv, Wo, wt);

    gemm_qkv<<<dim3(EMB / 128, MROWS / 128, 3), 256, GK_SMEM>>>(xt, wt, qb, kb, vb);

    flash_tc<<<dim3(S_LEN / 64, BATCH * NH), 128, FH_SMEM_BYTES>>>(qb, kb, vb, cb);

    gemm_out<<<dim3(EMB / 128, MROWS / 128), 256, GK_SMEM>>>(cb, wto, bo, out);
}